// round 1
// baseline (speedup 1.0000x reference)
#include <cuda_runtime.h>

#define NN 50000
#define EE 800000
#define RRR 2
#define LLL 2
#define DDD 128
#define GGG 64
#define CCC 8

// ---------------- scratch (static device globals; no allocation) ----------------
__device__ float g_xw0[NN * DDD];
__device__ float g_xw1[NN * DDD];
__device__ float g_agg[NN * DDD];
__device__ float g_deg[RRR * NN];
__device__ float g_isd[RRR * NN];
__device__ float g_pool[GGG * DDD];
__device__ float g_cnt[GGG];

// ---------------- degree / normalization ----------------
__global__ void k_init_deg() {
    int i = blockIdx.x * blockDim.x + threadIdx.x;
    if (i < RRR * NN) g_deg[i] = 1.0f;   // self-loop counts as 1
}

__global__ void k_count_deg(const int* __restrict__ ei) {
    int i = blockIdx.x * blockDim.x + threadIdx.x;
    if (i >= RRR * EE) return;
    int r = i / EE, e = i - r * EE;
    int dst = __ldg(ei + (size_t)r * 2 * EE + EE + e);
    atomicAdd(&g_deg[r * NN + dst], 1.0f);
}

__global__ void k_isd() {
    int i = blockIdx.x * blockDim.x + threadIdx.x;
    if (i < RRR * NN) g_isd[i] = rsqrtf(g_deg[i]);
}

// ---------------- fp32 GEMM: Out[N,128] = (relu?)A[N,128] @ W[128,128] ----------------
// 128x128 tile per block, 256 threads, 8x8 register tile per thread, K chunked by 16.
__global__ __launch_bounds__(256) void k_gemm(const float* __restrict__ A,
                                              const float* __restrict__ Wp,
                                              float* __restrict__ Out,
                                              int relu_in) {
    __shared__ float  As[128 * 17];     // [row][k], padded stride 17
    __shared__ float4 Bs[16 * 32];      // [k][col/4]

    int tid  = threadIdx.x;
    int row0 = blockIdx.x * 128;
    int tx   = tid & 15;                // 16 col-groups
    int ty8  = (tid >> 4) << 3;         // 16 row-groups of 8 rows

    float acc[8][8];
#pragma unroll
    for (int i = 0; i < 8; i++)
#pragma unroll
        for (int j = 0; j < 8; j++) acc[i][j] = 0.0f;

    for (int k0 = 0; k0 < 128; k0 += 16) {
        // load A tile: 128 rows x 16 k  (512 float4 slots, 2 per thread)
#pragma unroll
        for (int t = 0; t < 2; t++) {
            int idx  = tid + t * 256;
            int r    = idx >> 2;
            int c4   = (idx & 3) << 2;
            int grow = row0 + r;
            float4 v = make_float4(0.f, 0.f, 0.f, 0.f);
            if (grow < NN)
                v = *(const float4*)(A + (size_t)grow * 128 + k0 + c4);
            if (relu_in) {
                v.x = fmaxf(v.x, 0.f); v.y = fmaxf(v.y, 0.f);
                v.z = fmaxf(v.z, 0.f); v.w = fmaxf(v.w, 0.f);
            }
            As[r * 17 + c4 + 0] = v.x;
            As[r * 17 + c4 + 1] = v.y;
            As[r * 17 + c4 + 2] = v.z;
            As[r * 17 + c4 + 3] = v.w;
        }
        // load W tile: 16 k-rows x 128 cols (512 float4, 2 per thread)
#pragma unroll
        for (int t = 0; t < 2; t++) {
            int idx = tid + t * 256;
            int kr  = idx >> 5;
            int c4  = idx & 31;
            Bs[kr * 32 + c4] = *(const float4*)(Wp + (size_t)(k0 + kr) * 128 + c4 * 4);
        }
        __syncthreads();

#pragma unroll
        for (int kk = 0; kk < 16; kk++) {
            float a[8];
#pragma unroll
            for (int i = 0; i < 8; i++) a[i] = As[(ty8 + i) * 17 + kk];
            float4 b0 = Bs[kk * 32 + tx];
            float4 b1 = Bs[kk * 32 + 16 + tx];
#pragma unroll
            for (int i = 0; i < 8; i++) {
                acc[i][0] += a[i] * b0.x; acc[i][1] += a[i] * b0.y;
                acc[i][2] += a[i] * b0.z; acc[i][3] += a[i] * b0.w;
                acc[i][4] += a[i] * b1.x; acc[i][5] += a[i] * b1.y;
                acc[i][6] += a[i] * b1.z; acc[i][7] += a[i] * b1.w;
            }
        }
        __syncthreads();
    }

    int cb = tx * 4;
#pragma unroll
    for (int i = 0; i < 8; i++) {
        int row = row0 + ty8 + i;
        if (row < NN) {
            *(float4*)(Out + (size_t)row * 128 + cb) =
                make_float4(acc[i][0], acc[i][1], acc[i][2], acc[i][3]);
            *(float4*)(Out + (size_t)row * 128 + 64 + cb) =
                make_float4(acc[i][4], acc[i][5], acc[i][6], acc[i][7]);
        }
    }
}

// ---------------- self-loop + bias init of agg (no zeroing needed) ----------------
__global__ void k_self(const float* __restrict__ b_l, float4* __restrict__ agg) {
    int i = blockIdx.x * blockDim.x + threadIdx.x;  // over NN*32 float4s
    if (i >= NN * 32) return;
    int node = i >> 5, c = i & 31;
    float c0 = g_isd[node];        c0 *= c0;
    float c1 = g_isd[NN + node];   c1 *= c1;
    float4 x0 = ((const float4*)g_xw0)[i];
    float4 x1 = ((const float4*)g_xw1)[i];
    float4 b0 = ((const float4*)b_l)[c];
    float4 b1 = ((const float4*)(b_l + DDD))[c];
    float4 o;
    o.x = b0.x + b1.x + x0.x * c0 + x1.x * c1;
    o.y = b0.y + b1.y + x0.y * c0 + x1.y * c1;
    o.z = b0.z + b1.z + x0.z * c0 + x1.z * c1;
    o.w = b0.w + b1.w + x0.w * c0 + x1.w * c1;
    agg[i] = o;
}

// ---------------- edge scatter: warp per edge, v4 reduction atomics ----------------
__global__ void k_scatter(const float4* __restrict__ xw,
                          const float* __restrict__ isd,
                          const int* __restrict__ src,
                          const int* __restrict__ dst) {
    int t    = blockIdx.x * blockDim.x + threadIdx.x;
    int w    = t >> 5;
    int lane = t & 31;
    if (w >= EE) return;
    int s = __ldg(src + w);
    int d = __ldg(dst + w);
    float nrm = __ldg(isd + s) * __ldg(isd + d);
    float4 v = xw[(size_t)s * 32 + lane];
    float* p = g_agg + (size_t)d * 128 + lane * 4;
    asm volatile("red.global.add.v4.f32 [%0], {%1,%2,%3,%4};"
                 :: "l"(p), "f"(v.x * nrm), "f"(v.y * nrm),
                    "f"(v.z * nrm), "f"(v.w * nrm)
                 : "memory");
}

// ---------------- pooling ----------------
__global__ void k_pool_zero() {
    int i = blockIdx.x * blockDim.x + threadIdx.x;
    if (i < GGG * DDD) g_pool[i] = 0.f;
    if (i < GGG) g_cnt[i] = 0.f;
}

__global__ void k_pool(const int* __restrict__ batch) {
    int t    = blockIdx.x * blockDim.x + threadIdx.x;
    int w    = t >> 5;
    int lane = t & 31;
    if (w >= NN) return;
    int g = __ldg(batch + w);
    float4 v = ((const float4*)g_agg)[(size_t)w * 32 + lane];
    float* p = g_pool + (size_t)g * 128 + lane * 4;
    asm volatile("red.global.add.v4.f32 [%0], {%1,%2,%3,%4};"
                 :: "l"(p), "f"(v.x), "f"(v.y), "f"(v.z), "f"(v.w)
                 : "memory");
    if (lane == 0) atomicAdd(&g_cnt[g], 1.0f);
}

__global__ void k_final(const float* __restrict__ lw, const float* __restrict__ lb,
                        float* __restrict__ out) {
    int tid = threadIdx.x;
    if (tid >= GGG * CCC) return;
    int g = tid >> 3, c = tid & 7;
    float cnt = fmaxf(g_cnt[g], 1.0f);
    float s = 0.f;
#pragma unroll 8
    for (int k = 0; k < DDD; k++)
        s += g_pool[g * DDD + k] * __ldg(lw + k * CCC + c);
    out[tid] = s / cnt + __ldg(lb + c);
}

// ---------------- launch ----------------
extern "C" void kernel_launch(void* const* d_in, const int* in_sizes, int n_in,
                              void* d_out, int out_size) {
    const float* x     = (const float*)d_in[0];
    const float* W     = (const float*)d_in[1];   // [L,R,128,128]
    const float* b     = (const float*)d_in[2];   // [L,R,128]
    const float* lw    = (const float*)d_in[3];   // [128,8]
    const float* lb    = (const float*)d_in[4];   // [8]
    const int*   ei    = (const int*)d_in[5];     // [R,2,E]
    const int*   batch = (const int*)d_in[6];     // [N]
    float*       out   = (float*)d_out;           // [64,8]

    float *xw0, *xw1, *agg, *isd;
    cudaGetSymbolAddress((void**)&xw0, g_xw0);
    cudaGetSymbolAddress((void**)&xw1, g_xw1);
    cudaGetSymbolAddress((void**)&agg, g_agg);
    cudaGetSymbolAddress((void**)&isd, g_isd);

    const int* src0 = ei;
    const int* dst0 = ei + EE;
    const int* src1 = ei + (size_t)2 * EE;
    const int* dst1 = ei + (size_t)3 * EE;

    const int DDSQ = DDD * DDD;

    // degrees + inv sqrt
    k_init_deg<<<(RRR * NN + 255) / 256, 256>>>();
    k_count_deg<<<(RRR * EE + 255) / 256, 256>>>(ei);
    k_isd<<<(RRR * NN + 255) / 256, 256>>>();

    int gemm_blocks  = (NN + 127) / 128;
    int self_blocks  = (NN * 32 + 255) / 256;
    int scat_blocks  = (EE * 32 + 255) / 256;

    // ---- layer 0 ----
    k_gemm<<<gemm_blocks, 256>>>(x, W + 0 * DDSQ, xw0, 0);
    k_gemm<<<gemm_blocks, 256>>>(x, W + 1 * DDSQ, xw1, 0);
    k_self<<<self_blocks, 256>>>(b + 0 * RRR * DDD, (float4*)agg);
    k_scatter<<<scat_blocks, 256>>>((const float4*)xw0, isd,       src0, dst0);
    k_scatter<<<scat_blocks, 256>>>((const float4*)xw1, isd + NN,  src1, dst1);

    // ---- layer 1 (relu on input) ----
    k_gemm<<<gemm_blocks, 256>>>(agg, W + 2 * DDSQ, xw0, 1);
    k_gemm<<<gemm_blocks, 256>>>(agg, W + 3 * DDSQ, xw1, 1);
    k_self<<<self_blocks, 256>>>(b + 1 * RRR * DDD, (float4*)agg);
    k_scatter<<<scat_blocks, 256>>>((const float4*)xw0, isd,       src0, dst0);
    k_scatter<<<scat_blocks, 256>>>((const float4*)xw1, isd + NN,  src1, dst1);

    // ---- pool + classify ----
    k_pool_zero<<<(GGG * DDD + 255) / 256, 256>>>();
    k_pool<<<(NN * 32 + 255) / 256, 256>>>(batch);
    k_final<<<1, 512>>>(lw, lb, out);
}

// round 2
// speedup vs baseline: 1.7483x; 1.7483x over previous
#include <cuda_runtime.h>

#define NN 50000
#define EE 800000
#define DDD 128
#define GGG 64
#define CCC 8

// ---------------- scratch (static device globals) ----------------
__device__ float  g_xw0[NN * DDD];
__device__ float  g_xw1[NN * DDD];
__device__ float  g_agg[NN * DDD];
__device__ int    g_ecnt[2 * NN];        // per-relation dst histogram
__device__ float  g_isd[2 * NN];         // 1/sqrt(deg+1)
__device__ int    g_off[2 * NN];         // CSR offsets (relation-local)
__device__ int    g_cur[2 * NN];         // fill cursors
__device__ int    g_btot[2 * 64];        // scan block totals
__device__ int    g_boff[2 * 64];        // scan block offsets
__device__ float2 g_ebuf[2 * EE];        // (src as int bits, norm)
__device__ int    g_bcnt[GGG];           // batch histogram
__device__ float  g_pool[GGG * DDD];

// ---------------- zero pass ----------------
__global__ void k_zero() {
    int i = blockIdx.x * blockDim.x + threadIdx.x;
    if (i < 2 * NN) g_ecnt[i] = 0;
    if (i < GGG * DDD) g_pool[i] = 0.f;
    if (i < GGG) g_bcnt[i] = 0;
}

// ---------------- histograms: edge dst (both relations) + batch ----------------
__global__ void k_hist(const int* __restrict__ ei, const int* __restrict__ batch) {
    int i = blockIdx.x * blockDim.x + threadIdx.x;
    if (i < 2 * EE) {
        int r = (i >= EE) ? 1 : 0;
        int e = i - r * EE;
        int dst = __ldg(ei + (size_t)r * 2 * EE + EE + e);
        atomicAdd(&g_ecnt[r * NN + dst], 1);
    } else if (i < 2 * EE + NN) {
        int node = i - 2 * EE;
        atomicAdd(&g_bcnt[__ldg(batch + node)], 1);
    }
}

__global__ void k_isd() {
    int i = blockIdx.x * blockDim.x + threadIdx.x;
    if (i < 2 * NN) g_isd[i] = rsqrtf((float)g_ecnt[i] + 1.0f);
}

// ---------------- exclusive scan of g_ecnt -> g_off (3 phases) ----------------
// Phase A: per-block (1024 elems) exclusive scan + block total.
__global__ __launch_bounds__(256) void k_scanA() {
    __shared__ int sm[256];
    int r  = blockIdx.y;
    int bx = blockIdx.x;
    int t  = threadIdx.x;
    int base = bx * 1024 + t * 4;
    int c[4];
#pragma unroll
    for (int j = 0; j < 4; j++) {
        int n = base + j;
        c[j] = (n < NN) ? g_ecnt[r * NN + n] : 0;
    }
    int s = c[0] + c[1] + c[2] + c[3];
    sm[t] = s;
    __syncthreads();
#pragma unroll
    for (int o = 1; o < 256; o <<= 1) {
        int v = (t >= o) ? sm[t - o] : 0;
        __syncthreads();
        sm[t] += v;
        __syncthreads();
    }
    int excl = sm[t] - s;
    int p = excl;
#pragma unroll
    for (int j = 0; j < 4; j++) {
        int n = base + j;
        if (n < NN) g_off[r * NN + n] = p;
        p += c[j];
    }
    if (t == 255) g_btot[r * 64 + bx] = sm[255];
}

// Phase B: scan the 49 block totals per relation (serial, tiny).
__global__ void k_scanB() {
    int t = threadIdx.x;
    if (t < 2) {
        int s = 0;
        for (int i = 0; i < 49; i++) {
            g_boff[t * 64 + i] = s;
            s += g_btot[t * 64 + i];
        }
    }
}

// Phase C: add block offsets, init cursors.
__global__ void k_scanC() {
    int i = blockIdx.x * blockDim.x + threadIdx.x;
    if (i >= 2 * NN) return;
    int r = (i >= NN) ? 1 : 0;
    int n = i - r * NN;
    int v = g_off[i] + g_boff[r * 64 + (n >> 10)];
    g_off[i] = v;
    g_cur[i] = v;
}

// ---------------- edge fill: CSR buckets with precomputed norm ----------------
__global__ void k_fill(const int* __restrict__ ei) {
    int i = blockIdx.x * blockDim.x + threadIdx.x;
    if (i >= 2 * EE) return;
    int r = (i >= EE) ? 1 : 0;
    int e = i - r * EE;
    int s = __ldg(ei + (size_t)r * 2 * EE + e);
    int d = __ldg(ei + (size_t)r * 2 * EE + EE + e);
    float nrm = g_isd[r * NN + s] * g_isd[r * NN + d];
    int pos = atomicAdd(&g_cur[r * NN + d], 1);
    g_ebuf[(size_t)r * EE + pos] = make_float2(__int_as_float(s), nrm);
}

// ---------------- fused pair GEMM: out_r = A @ W_r, r = blockIdx.y ----------------
__global__ __launch_bounds__(256, 2) void k_gemm(const float* __restrict__ A,
                                                 const float* __restrict__ Wl,
                                                 float* __restrict__ out0,
                                                 float* __restrict__ out1) {
    __shared__ float  As[16][132];      // [k][row], transposed
    __shared__ float4 Bs[16][32];       // [k][col/4]

    const float* Wp  = Wl + (size_t)blockIdx.y * DDD * DDD;
    float*       Out = blockIdx.y ? out1 : out0;

    int tid  = threadIdx.x;
    int row0 = blockIdx.x * 128;
    int tx   = tid & 15;
    int ty8  = (tid >> 4) << 3;

    float acc[8][8];
#pragma unroll
    for (int i = 0; i < 8; i++)
#pragma unroll
        for (int j = 0; j < 8; j++) acc[i][j] = 0.0f;

    for (int k0 = 0; k0 < 128; k0 += 16) {
#pragma unroll
        for (int t = 0; t < 2; t++) {
            int idx = tid + t * 256;
            int r   = idx >> 2;
            int c4  = (idx & 3) << 2;
            int grow = row0 + r;
            float4 v = make_float4(0.f, 0.f, 0.f, 0.f);
            if (grow < NN)
                v = *(const float4*)(A + (size_t)grow * 128 + k0 + c4);
            As[c4 + 0][r] = v.x;
            As[c4 + 1][r] = v.y;
            As[c4 + 2][r] = v.z;
            As[c4 + 3][r] = v.w;
        }
#pragma unroll
        for (int t = 0; t < 2; t++) {
            int idx = tid + t * 256;
            int kr  = idx >> 5;
            int c4  = idx & 31;
            Bs[kr][c4] = *(const float4*)(Wp + (size_t)(k0 + kr) * 128 + c4 * 4);
        }
        __syncthreads();

#pragma unroll
        for (int kk = 0; kk < 16; kk++) {
            float4 alo = *(const float4*)&As[kk][ty8];
            float4 ahi = *(const float4*)&As[kk][ty8 + 4];
            float4 b0  = Bs[kk][tx];
            float4 b1  = Bs[kk][16 + tx];
            float a[8] = {alo.x, alo.y, alo.z, alo.w, ahi.x, ahi.y, ahi.z, ahi.w};
#pragma unroll
            for (int i = 0; i < 8; i++) {
                acc[i][0] += a[i] * b0.x; acc[i][1] += a[i] * b0.y;
                acc[i][2] += a[i] * b0.z; acc[i][3] += a[i] * b0.w;
                acc[i][4] += a[i] * b1.x; acc[i][5] += a[i] * b1.y;
                acc[i][6] += a[i] * b1.z; acc[i][7] += a[i] * b1.w;
            }
        }
        __syncthreads();
    }

    int cb = tx * 4;
#pragma unroll
    for (int i = 0; i < 8; i++) {
        int row = row0 + ty8 + i;
        if (row < NN) {
            *(float4*)(Out + (size_t)row * 128 + cb) =
                make_float4(acc[i][0], acc[i][1], acc[i][2], acc[i][3]);
            *(float4*)(Out + (size_t)row * 128 + 64 + cb) =
                make_float4(acc[i][4], acc[i][5], acc[i][6], acc[i][7]);
        }
    }
}

// ---------------- fused gather: CSR sum + self + bias (+relu / +pool-red) ----------------
__global__ void k_gather(const float* __restrict__ bias_l,
                         const int* __restrict__ batch, int layer) {
    int t    = blockIdx.x * blockDim.x + threadIdx.x;
    int d    = t >> 5;
    int lane = t & 31;
    if (d >= NN) return;

    float4 b0 = ((const float4*)bias_l)[lane];
    float4 b1 = ((const float4*)(bias_l + DDD))[lane];
    float4 acc = make_float4(b0.x + b1.x, b0.y + b1.y, b0.z + b1.z, b0.w + b1.w);

#pragma unroll
    for (int r = 0; r < 2; r++) {
        const float4* xw = (const float4*)(r ? g_xw1 : g_xw0);
        float isd_d = g_isd[r * NN + d];
        // self-loop term: coeff = 1/(deg+1)
        float4 xs = xw[(size_t)d * 32 + lane];
        float c = isd_d * isd_d;
        acc.x += xs.x * c; acc.y += xs.y * c; acc.z += xs.z * c; acc.w += xs.w * c;

        int e  = g_off[r * NN + d];
        int e1 = (d < NN - 1) ? g_off[r * NN + d + 1] : EE;
        const float2* eb = g_ebuf + (size_t)r * EE;
        for (; e + 1 < e1; e += 2) {
            float2 ea = eb[e];
            float2 ec = eb[e + 1];
            int sa = __float_as_int(ea.x);
            int sc = __float_as_int(ec.x);
            float4 va = xw[(size_t)sa * 32 + lane];
            float4 vc = xw[(size_t)sc * 32 + lane];
            acc.x += va.x * ea.y + vc.x * ec.y;
            acc.y += va.y * ea.y + vc.y * ec.y;
            acc.z += va.z * ea.y + vc.z * ec.y;
            acc.w += va.w * ea.y + vc.w * ec.y;
        }
        if (e < e1) {
            float2 ea = eb[e];
            int sa = __float_as_int(ea.x);
            float4 va = xw[(size_t)sa * 32 + lane];
            acc.x += va.x * ea.y; acc.y += va.y * ea.y;
            acc.z += va.z * ea.y; acc.w += va.w * ea.y;
        }
    }

    if (layer == 0) {
        acc.x = fmaxf(acc.x, 0.f); acc.y = fmaxf(acc.y, 0.f);
        acc.z = fmaxf(acc.z, 0.f); acc.w = fmaxf(acc.w, 0.f);
        ((float4*)g_agg)[(size_t)d * 32 + lane] = acc;
    } else {
        int g = __ldg(batch + d);
        float* p = g_pool + (size_t)g * 128 + lane * 4;
        asm volatile("red.global.add.v4.f32 [%0], {%1,%2,%3,%4};"
                     :: "l"(p), "f"(acc.x), "f"(acc.y), "f"(acc.z), "f"(acc.w)
                     : "memory");
    }
}

// ---------------- final linear ----------------
__global__ void k_final(const float* __restrict__ lw, const float* __restrict__ lb,
                        float* __restrict__ out) {
    int tid = threadIdx.x;
    if (tid >= GGG * CCC) return;
    int g = tid >> 3, c = tid & 7;
    float cnt = fmaxf((float)g_bcnt[g], 1.0f);
    float s = 0.f;
#pragma unroll 8
    for (int k = 0; k < DDD; k++)
        s += g_pool[g * DDD + k] * __ldg(lw + k * CCC + c);
    out[tid] = s / cnt + __ldg(lb + c);
}

// ---------------- launch ----------------
extern "C" void kernel_launch(void* const* d_in, const int* in_sizes, int n_in,
                              void* d_out, int out_size) {
    const float* x     = (const float*)d_in[0];
    const float* W     = (const float*)d_in[1];   // [2,2,128,128]
    const float* b     = (const float*)d_in[2];   // [2,2,128]
    const float* lw    = (const float*)d_in[3];   // [128,8]
    const float* lb    = (const float*)d_in[4];   // [8]
    const int*   ei    = (const int*)d_in[5];     // [2,2,E]
    const int*   batch = (const int*)d_in[6];     // [N]
    float*       out   = (float*)d_out;           // [64,8]

    float *xw0, *xw1, *agg;
    cudaGetSymbolAddress((void**)&xw0, g_xw0);
    cudaGetSymbolAddress((void**)&xw1, g_xw1);
    cudaGetSymbolAddress((void**)&agg, g_agg);

    const int DDSQ = DDD * DDD;

    // prep: histograms, normalization, CSR
    k_zero<<<(2 * NN + 255) / 256, 256>>>();
    k_hist<<<(2 * EE + NN + 255) / 256, 256>>>(ei, batch);
    k_isd<<<(2 * NN + 255) / 256, 256>>>();
    k_scanA<<<dim3(49, 2), 256>>>();
    k_scanB<<<1, 32>>>();
    k_scanC<<<(2 * NN + 255) / 256, 256>>>();
    k_fill<<<(2 * EE + 255) / 256, 256>>>(ei);

    int gemm_blocks   = (NN + 127) / 128;
    int gather_blocks = (NN * 32 + 255) / 256;

    // layer 0
    k_gemm<<<dim3(gemm_blocks, 2), 256>>>(x, W, xw0, xw1);
    k_gather<<<gather_blocks, 256>>>(b, batch, 0);

    // layer 1
    k_gemm<<<dim3(gemm_blocks, 2), 256>>>(agg, W + 2 * DDSQ, xw0, xw1);
    k_gather<<<gather_blocks, 256>>>(b + 2 * DDD, batch, 1);

    // classify
    k_final<<<1, 512>>>(lw, lb, out);
}

// round 4
// speedup vs baseline: 2.3518x; 1.3452x over previous
#include <cuda_runtime.h>
#include <cuda_fp16.h>
#include <cuda_bf16.h>
#include <cstdint>

#define NN 50000
#define EE 800000
#define DDD 128
#define GGG 64
#define CCC 8

// ---------------- scratch ----------------
__device__ __half        g_h16[NN * DDD];        // fp16 feature table
__device__ __nv_bfloat16 g_ahi[NN * 256];        // A split hi  [node][256]
__device__ __nv_bfloat16 g_alo[NN * 256];        // A split lo
__device__ __nv_bfloat16 g_whi[2 * 128 * 256];   // Wt split hi [layer][n][k]
__device__ __nv_bfloat16 g_wlo[2 * 128 * 256];
__device__ int    g_ecnt[2 * NN];
__device__ float  g_isd[2 * NN];
__device__ int    g_off[NN];
__device__ int    g_cur[NN];
__device__ int    g_btot[64];
__device__ int    g_boff[64];
__device__ float2 g_ebuf[2 * EE];                // (src | r<<30, isd_r[src])
__device__ int    g_bcnt[GGG];
__device__ float  g_pool[GGG * DDD];

// ================= helpers =================
__device__ __forceinline__ unsigned smem_u32(const void* p) {
    unsigned a;
    asm("{ .reg .u64 t; cvta.to.shared.u64 t, %1; cvt.u32.u64 %0, t; }" : "=r"(a) : "l"(p));
    return a;
}
__device__ __forceinline__ void cp16(unsigned dst, const void* gsrc, unsigned srcsize) {
    asm volatile("cp.async.cg.shared.global [%0], [%1], 16, %2;"
                 :: "r"(dst), "l"(__cvta_generic_to_global((void*)gsrc)), "r"(srcsize) : "memory");
}
__device__ __forceinline__ void cp_commit() { asm volatile("cp.async.commit_group;" ::: "memory"); }
template <int N> __device__ __forceinline__ void cp_wait() {
    asm volatile("cp.async.wait_group %0;" :: "n"(N) : "memory");
}
__device__ __forceinline__ void ldm_x4(unsigned& r0, unsigned& r1, unsigned& r2, unsigned& r3,
                                       unsigned addr) {
    asm volatile("ldmatrix.sync.aligned.m8n8.x4.shared.b16 {%0,%1,%2,%3}, [%4];"
                 : "=r"(r0), "=r"(r1), "=r"(r2), "=r"(r3) : "r"(addr));
}
__device__ __forceinline__ void mma_bf16(float* d, const unsigned* a, const unsigned* b) {
    asm volatile("mma.sync.aligned.m16n8k16.row.col.f32.bf16.bf16.f32 "
                 "{%0,%1,%2,%3},{%4,%5,%6,%7},{%8,%9},{%0,%1,%2,%3};"
                 : "+f"(d[0]), "+f"(d[1]), "+f"(d[2]), "+f"(d[3])
                 : "r"(a[0]), "r"(a[1]), "r"(a[2]), "r"(a[3]), "r"(b[0]), "r"(b[1]));
}

// ================= prep kernels =================
__global__ void k_zero() {
    int i = blockIdx.x * blockDim.x + threadIdx.x;
    if (i < 2 * NN) g_ecnt[i] = 0;
    if (i < GGG * DDD) g_pool[i] = 0.f;
    if (i < GGG) g_bcnt[i] = 0;
}

__global__ void k_hist(const int* __restrict__ ei, const int* __restrict__ batch) {
    int i = blockIdx.x * blockDim.x + threadIdx.x;
    if (i < 2 * EE) {
        int r = (i >= EE) ? 1 : 0;
        int e = i - r * EE;
        int dst = __ldg(ei + (size_t)r * 2 * EE + EE + e);
        atomicAdd(&g_ecnt[r * NN + dst], 1);
    } else if (i < 2 * EE + NN) {
        atomicAdd(&g_bcnt[__ldg(batch + i - 2 * EE)], 1);
    }
}

__global__ void k_isd() {
    int i = blockIdx.x * blockDim.x + threadIdx.x;
    if (i < 2 * NN) g_isd[i] = rsqrtf((float)g_ecnt[i] + 1.0f);
}

__global__ __launch_bounds__(256) void k_scanA() {
    __shared__ int sm[256];
    int bx = blockIdx.x, t = threadIdx.x;
    int base = bx * 1024 + t * 4;
    int c[4];
#pragma unroll
    for (int j = 0; j < 4; j++) {
        int n = base + j;
        c[j] = (n < NN) ? (g_ecnt[n] + g_ecnt[NN + n]) : 0;
    }
    int s = c[0] + c[1] + c[2] + c[3];
    sm[t] = s;
    __syncthreads();
#pragma unroll
    for (int o = 1; o < 256; o <<= 1) {
        int v = (t >= o) ? sm[t - o] : 0;
        __syncthreads();
        sm[t] += v;
        __syncthreads();
    }
    int p = sm[t] - s;
#pragma unroll
    for (int j = 0; j < 4; j++) {
        int n = base + j;
        if (n < NN) g_off[n] = p;
        p += c[j];
    }
    if (t == 255) g_btot[bx] = sm[255];
}

__global__ void k_scanB() {
    if (threadIdx.x == 0) {
        int s = 0;
        for (int i = 0; i < 49; i++) { g_boff[i] = s; s += g_btot[i]; }
    }
}

__global__ void k_scanC() {
    int i = blockIdx.x * blockDim.x + threadIdx.x;
    if (i >= NN) return;
    int v = g_off[i] + g_boff[i >> 10];
    g_off[i] = v;
    g_cur[i] = v;
}

__global__ void k_fill(const int* __restrict__ ei) {
    int i = blockIdx.x * blockDim.x + threadIdx.x;
    if (i >= 2 * EE) return;
    int r = (i >= EE) ? 1 : 0;
    int e = i - r * EE;
    int s = __ldg(ei + (size_t)r * 2 * EE + e);
    int d = __ldg(ei + (size_t)r * 2 * EE + EE + e);
    float nrm = g_isd[r * NN + s];
    int pos = atomicAdd(&g_cur[d], 1);
    g_ebuf[pos] = make_float2(__int_as_float(s | (r << 30)), nrm);
}

__global__ void k_cvt(const float* __restrict__ x) {
    int i = blockIdx.x * blockDim.x + threadIdx.x;
    if (i >= NN * 32) return;
    float4 v = ((const float4*)x)[i];
    __half2 a = __floats2half2_rn(v.x, v.y);
    __half2 b = __floats2half2_rn(v.z, v.w);
    ((uint2*)g_h16)[i] = make_uint2(*(unsigned*)&a, *(unsigned*)&b);
}

// build transposed split weights: Wt[l][n][k], k = r*128 + kd
__global__ void k_wsplit(const float* __restrict__ W) {
    int i = blockIdx.x * blockDim.x + threadIdx.x;
    if (i >= 2 * 128 * 256) return;
    int l = i >> 15;
    int n = (i >> 8) & 127;
    int k = i & 255;
    int r = k >> 7, kd = k & 127;
    float v = __ldg(W + (((size_t)(l * 2 + r) * 128 + kd) * 128 + n));
    __nv_bfloat16 h = __float2bfloat16(v);
    g_whi[i] = h;
    g_wlo[i] = __float2bfloat16(v - __bfloat162float(h));
}

// ================= gather: h16 -> A hi/lo [N][256] =================
__global__ __launch_bounds__(256) void k_gather() {
    int t = blockIdx.x * blockDim.x + threadIdx.x;
    int d = t >> 4;
    int l16 = t & 15;
    if (d >= NN) return;

    float a0[8], a1[8];
#pragma unroll
    for (int j = 0; j < 8; j++) { a0[j] = 0.f; a1[j] = 0.f; }

    const uint4* h = (const uint4*)g_h16;

    int e  = g_off[d];
    int e1 = (d < NN - 1) ? g_off[d + 1] : 2 * EE;

    for (; e < e1; e++) {
        float2 ent = g_ebuf[e];
        int bits = __float_as_int(ent.x);
        int r = (bits >> 30) & 1;
        int s = bits & 0x3FFFFFFF;
        uint4 v = h[(size_t)s * 16 + l16];
        const __half2* hp = (const __half2*)&v;
        float2 f0 = __half22float2(hp[0]);
        float2 f1 = __half22float2(hp[1]);
        float2 f2 = __half22float2(hp[2]);
        float2 f3 = __half22float2(hp[3]);
        float f[8] = {f0.x, f0.y, f1.x, f1.y, f2.x, f2.y, f3.x, f3.y};
        float n0 = r ? 0.f : ent.y;
        float n1 = r ? ent.y : 0.f;
#pragma unroll
        for (int j = 0; j < 8; j++) { a0[j] += n0 * f[j]; a1[j] += n1 * f[j]; }
    }

    uint4 sv = h[(size_t)d * 16 + l16];
    const __half2* sp = (const __half2*)&sv;
    float2 s0 = __half22float2(sp[0]);
    float2 s1 = __half22float2(sp[1]);
    float2 s2 = __half22float2(sp[2]);
    float2 s3 = __half22float2(sp[3]);
    float hs[8] = {s0.x, s0.y, s1.x, s1.y, s2.x, s2.y, s3.x, s3.y};
    float i0 = g_isd[d], i1 = g_isd[NN + d];

    union { uint4 q; unsigned short s[8]; } h0, l0, h1, l1;
#pragma unroll
    for (int j = 0; j < 8; j++) {
        float o0 = i0 * a0[j] + i0 * i0 * hs[j];
        float o1 = i1 * a1[j] + i1 * i1 * hs[j];
        __nv_bfloat16 b0 = __float2bfloat16(o0);
        __nv_bfloat16 b1 = __float2bfloat16(o1);
        h0.s[j] = __bfloat16_as_ushort(b0);
        l0.s[j] = __bfloat16_as_ushort(__float2bfloat16(o0 - __bfloat162float(b0)));
        h1.s[j] = __bfloat16_as_ushort(b1);
        l1.s[j] = __bfloat16_as_ushort(__float2bfloat16(o1 - __bfloat162float(b1)));
    }
    size_t base = (size_t)d * 256 + l16 * 8;
    *(uint4*)(g_ahi + base)       = h0.q;
    *(uint4*)(g_alo + base)       = l0.q;
    *(uint4*)(g_ahi + base + 128) = h1.q;
    *(uint4*)(g_alo + base + 128) = l1.q;
}

// ================= mma.sync GEMM: C[128-tile,128] = A[.,256] @ Wt^T + bias =================
// smem: buf0 @0 (32KB), buf1 @32768, bias @65536 (512B)
// buffer layout: Ah @0, Al @8192, Bh @16384, Bl @24576; rows of 64B (32 bf16),
// 16B chunks xor-swizzled by ((row>>1)&3).
#define MMA_SMEM (65536 + 512)

__device__ __forceinline__ void load_chunk(unsigned sbuf, int row0, int kc, int layer, int tid) {
    const __nv_bfloat16* wh = g_whi + (size_t)layer * 32768;
    const __nv_bfloat16* wl = g_wlo + (size_t)layer * 32768;
#pragma unroll
    for (int t = 0; t < 8; t++) {
        int cid = tid + t * 256;
        int reg = cid >> 9;
        int idx = cid & 511;
        int row = idx >> 2;
        int ch  = idx & 3;
        unsigned dst = sbuf + reg * 8192 + row * 64 + ((ch ^ ((row >> 1) & 3)) << 4);
        if (reg < 2) {
            int grow = row0 + row;
            unsigned ok = (grow < NN) ? 16u : 0u;
            int gr = (grow < NN) ? grow : (NN - 1);
            const __nv_bfloat16* src = (reg == 0 ? g_ahi : g_alo) + (size_t)gr * 256 + kc * 32 + ch * 8;
            cp16(dst, src, ok);
        } else {
            const __nv_bfloat16* src = (reg == 2 ? wh : wl) + (size_t)row * 256 + kc * 32 + ch * 8;
            cp16(dst, src, 16u);
        }
    }
}

__global__ __launch_bounds__(256) void k_mma(const float* __restrict__ bias,
                                             const int* __restrict__ batch,
                                             int layer) {
    extern __shared__ char smem[];
    unsigned sb = smem_u32(smem);
    int tid  = threadIdx.x;
    int lane = tid & 31;
    int wid  = tid >> 5;
    int wm   = wid & 1;          // 2 warps along M
    int wn   = wid >> 1;         // 4 warps along N
    int row0 = blockIdx.x * 128;

    float* bias_s = (float*)(smem + 65536);
    if (tid < 128) bias_s[tid] = __ldg(bias + tid) + __ldg(bias + 128 + tid);

    float acc[4][4][4];
#pragma unroll
    for (int mt = 0; mt < 4; mt++)
#pragma unroll
        for (int nt = 0; nt < 4; nt++)
#pragma unroll
            for (int q = 0; q < 4; q++) acc[mt][nt][q] = 0.f;

    load_chunk(sb, row0, 0, layer, tid);
    cp_commit();

    for (int c = 0; c < 8; c++) {
        if (c + 1 < 8) {
            load_chunk(sb + ((c + 1) & 1) * 32768, row0, c + 1, layer, tid);
            cp_commit();
            cp_wait<1>();
        } else {
            cp_wait<0>();
        }
        __syncthreads();

        unsigned sbuf = sb + (c & 1) * 32768;
#pragma unroll
        for (int s = 0; s < 2; s++) {
            unsigned ah[4][4], al[4][4], bh[4][2], bl[4][2];
            // A fragments (hi & lo)
#pragma unroll
            for (int mt = 0; mt < 4; mt++) {
                int rl = wm * 64 + mt * 16 + ((lane >> 3) & 1) * 8 + (lane & 7);
                int ch = 2 * s + (lane >> 4);
                unsigned ad = sbuf + rl * 64 + ((ch ^ ((rl >> 1) & 3)) << 4);
                ldm_x4(ah[mt][0], ah[mt][1], ah[mt][2], ah[mt][3], ad);
                ldm_x4(al[mt][0], al[mt][1], al[mt][2], al[mt][3], ad + 8192);
            }
            // B fragments: each x4 covers 2 n-tiles
#pragma unroll
            for (int p = 0; p < 2; p++) {
                int rl = wn * 32 + p * 16 + ((lane >> 4) & 1) * 8 + (lane & 7);
                int ch = 2 * s + ((lane >> 3) & 1);
                unsigned bd = sbuf + 16384 + rl * 64 + ((ch ^ ((rl >> 1) & 3)) << 4);
                unsigned r0, r1, r2, r3;
                ldm_x4(r0, r1, r2, r3, bd);
                bh[2 * p][0] = r0; bh[2 * p][1] = r1;
                bh[2 * p + 1][0] = r2; bh[2 * p + 1][1] = r3;
                ldm_x4(r0, r1, r2, r3, bd + 8192);
                bl[2 * p][0] = r0; bl[2 * p][1] = r1;
                bl[2 * p + 1][0] = r2; bl[2 * p + 1][1] = r3;
            }
#pragma unroll
            for (int mt = 0; mt < 4; mt++)
#pragma unroll
                for (int nt = 0; nt < 4; nt++) {
                    mma_bf16(acc[mt][nt], ah[mt], bh[nt]);
                    mma_bf16(acc[mt][nt], ah[mt], bl[nt]);
                    mma_bf16(acc[mt][nt], al[mt], bh[nt]);
                }
        }
        __syncthreads();
    }

    // ---- epilogue ----
#pragma unroll
    for (int mt = 0; mt < 4; mt++) {
        int gm0 = row0 + wm * 64 + mt * 16 + (lane >> 2);
#pragma unroll
        for (int half = 0; half < 2; half++) {
            int gm = gm0 + half * 8;
            if (gm >= NN) continue;
            if (layer == 0) {
#pragma unroll
                for (int nt = 0; nt < 4; nt++) {
                    int cn = wn * 32 + nt * 8 + (lane & 3) * 2;
                    float v0 = fmaxf(acc[mt][nt][half * 2 + 0] + bias_s[cn], 0.f);
                    float v1 = fmaxf(acc[mt][nt][half * 2 + 1] + bias_s[cn + 1], 0.f);
                    __half2 hh = __floats2half2_rn(v0, v1);
                    *(__half2*)(g_h16 + (size_t)gm * 128 + cn) = hh;
                }
            } else {
                int g = __ldg(batch + gm);
#pragma unroll
                for (int nt = 0; nt < 4; nt++) {
                    int cn = wn * 32 + nt * 8 + (lane & 3) * 2;
                    float v0 = acc[mt][nt][half * 2 + 0] + bias_s[cn];
                    float v1 = acc[mt][nt][half * 2 + 1] + bias_s[cn + 1];
                    float* p = g_pool + (size_t)g * 128 + cn;
                    asm volatile("red.global.add.v2.f32 [%0], {%1,%2};"
                                 :: "l"(p), "f"(v0), "f"(v1) : "memory");
                }
            }
        }
    }
}

// ================= final linear =================
__global__ void k_final(const float* __restrict__ lw, const float* __restrict__ lb,
                        float* __restrict__ out) {
    int tid = threadIdx.x;
    if (tid >= GGG * CCC) return;
    int g = tid >> 3, c = tid & 7;
    float cnt = fmaxf((float)g_bcnt[g], 1.0f);
    float s = 0.f;
#pragma unroll 8
    for (int k = 0; k < DDD; k++)
        s += g_pool[g * DDD + k] * __ldg(lw + k * CCC + c);
    out[tid] = s / cnt + __ldg(lb + c);
}

// ================= launch =================
extern "C" void kernel_launch(void* const* d_in, const int* in_sizes, int n_in,
                              void* d_out, int out_size) {
    const float* x     = (const float*)d_in[0];
    const float* W     = (const float*)d_in[1];
    const float* b     = (const float*)d_in[2];
    const float* lw    = (const float*)d_in[3];
    const float* lb    = (const float*)d_in[4];
    const int*   ei    = (const int*)d_in[5];
    const int*   batch = (const int*)d_in[6];
    float*       out   = (float*)d_out;

    cudaFuncSetAttribute(k_mma, cudaFuncAttributeMaxDynamicSharedMemorySize, MMA_SMEM);

    // prep
    k_zero<<<(2 * NN + 255) / 256, 256>>>();
    k_hist<<<(2 * EE + NN + 255) / 256, 256>>>(ei, batch);
    k_isd<<<(2 * NN + 255) / 256, 256>>>();
    k_scanA<<<49, 256>>>();
    k_scanB<<<1, 32>>>();
    k_scanC<<<(NN + 255) / 256, 256>>>();
    k_fill<<<(2 * EE + 255) / 256, 256>>>(ei);
    k_cvt<<<(NN * 32 + 255) / 256, 256>>>(x);
    k_wsplit<<<(2 * 128 * 256 + 255) / 256, 256>>>(W);

    int mma_blocks = (NN + 127) / 128;
    int gat_blocks = (NN * 16 + 255) / 256;

    // layer 0
    k_gather<<<gat_blocks, 256>>>();
    k_mma<<<mma_blocks, 256, MMA_SMEM>>>(b, batch, 0);

    // layer 1
    k_gather<<<gat_blocks, 256>>>();
    k_mma<<<mma_blocks, 256, MMA_SMEM>>>(b + 2 * DDD, batch, 1);

    // classify
    k_final<<<1, 512>>>(lw, lb, out);
}

// round 5
// speedup vs baseline: 2.7912x; 1.1868x over previous
#include <cuda_runtime.h>
#include <cuda_fp16.h>
#include <cstdint>

#define NN 50000
#define EE 800000
#define DDD 128
#define GGG 64
#define CCC 8

// ---------------- scratch ----------------
__device__ __half g_h16[NN * DDD];        // fp16 feature table (layer input)
__device__ __half g_a16[NN * 256];        // aggregated A [node][256] fp16
__device__ __half g_w16[2 * 128 * 256];   // Wt fp16 [layer][n][k]
__device__ int    g_ecnt[2 * NN];
__device__ float  g_isd[2 * NN];
__device__ int    g_off[NN];
__device__ int    g_cur[NN];
__device__ int    g_btot[64];
__device__ int    g_boff[64];
__device__ float2 g_ebuf[2 * EE];         // (src | r<<30, isd_r[src])
__device__ int    g_bcnt[GGG];
__device__ float  g_pool[GGG * DDD];

// ================= helpers =================
__device__ __forceinline__ unsigned smem_u32(const void* p) {
    unsigned a;
    asm("{ .reg .u64 t; cvta.to.shared.u64 t, %1; cvt.u32.u64 %0, t; }" : "=r"(a) : "l"(p));
    return a;
}
__device__ __forceinline__ void cp16(unsigned dst, const void* gsrc, unsigned srcsize) {
    asm volatile("cp.async.cg.shared.global [%0], [%1], 16, %2;"
                 :: "r"(dst), "l"(__cvta_generic_to_global((void*)gsrc)), "r"(srcsize) : "memory");
}
__device__ __forceinline__ void cp_commit() { asm volatile("cp.async.commit_group;" ::: "memory"); }
template <int N> __device__ __forceinline__ void cp_wait() {
    asm volatile("cp.async.wait_group %0;" :: "n"(N) : "memory");
}
__device__ __forceinline__ void ldm_x4(unsigned& r0, unsigned& r1, unsigned& r2, unsigned& r3,
                                       unsigned addr) {
    asm volatile("ldmatrix.sync.aligned.m8n8.x4.shared.b16 {%0,%1,%2,%3}, [%4];"
                 : "=r"(r0), "=r"(r1), "=r"(r2), "=r"(r3) : "r"(addr));
}
__device__ __forceinline__ void mma_f16(float* d, const unsigned* a, const unsigned* b) {
    asm volatile("mma.sync.aligned.m16n8k16.row.col.f32.f16.f16.f32 "
                 "{%0,%1,%2,%3},{%4,%5,%6,%7},{%8,%9},{%0,%1,%2,%3};"
                 : "+f"(d[0]), "+f"(d[1]), "+f"(d[2]), "+f"(d[3])
                 : "r"(a[0]), "r"(a[1]), "r"(a[2]), "r"(a[3]), "r"(b[0]), "r"(b[1]));
}
// packed f32x2 (Blackwell)
__device__ __forceinline__ unsigned long long pack2(float lo, float hi) {
    unsigned long long r;
    asm("mov.b64 %0, {%1,%2};" : "=l"(r) : "f"(lo), "f"(hi));
    return r;
}
__device__ __forceinline__ float2 unpack2(unsigned long long v) {
    float2 f;
    asm("mov.b64 {%0,%1}, %2;" : "=f"(f.x), "=f"(f.y) : "l"(v));
    return f;
}
__device__ __forceinline__ void fma2(unsigned long long& a, unsigned long long x,
                                     unsigned long long n) {
    asm("fma.rn.f32x2 %0, %1, %2, %0;" : "+l"(a) : "l"(x), "l"(n));
}

// ================= prep kernels =================
__global__ void k_zero() {
    int i = blockIdx.x * blockDim.x + threadIdx.x;
    if (i < 2 * NN) g_ecnt[i] = 0;
    if (i < GGG * DDD) g_pool[i] = 0.f;
    if (i < GGG) g_bcnt[i] = 0;
}

__global__ void k_hist(const int* __restrict__ ei, const int* __restrict__ batch) {
    int i = blockIdx.x * blockDim.x + threadIdx.x;
    if (i < 2 * EE) {
        int r = (i >= EE) ? 1 : 0;
        int e = i - r * EE;
        int dst = __ldg(ei + (size_t)r * 2 * EE + EE + e);
        atomicAdd(&g_ecnt[r * NN + dst], 1);
    } else if (i < 2 * EE + NN) {
        atomicAdd(&g_bcnt[__ldg(batch + i - 2 * EE)], 1);
    }
}

// scan (combined degree) + isd fused
__global__ __launch_bounds__(256) void k_scanA() {
    __shared__ int sm[256];
    int bx = blockIdx.x, t = threadIdx.x;
    int base = bx * 1024 + t * 4;
    int c[4];
#pragma unroll
    for (int j = 0; j < 4; j++) {
        int n = base + j;
        if (n < NN) {
            int c0 = g_ecnt[n], c1 = g_ecnt[NN + n];
            g_isd[n]      = rsqrtf((float)c0 + 1.0f);
            g_isd[NN + n] = rsqrtf((float)c1 + 1.0f);
            c[j] = c0 + c1;
        } else c[j] = 0;
    }
    int s = c[0] + c[1] + c[2] + c[3];
    sm[t] = s;
    __syncthreads();
#pragma unroll
    for (int o = 1; o < 256; o <<= 1) {
        int v = (t >= o) ? sm[t - o] : 0;
        __syncthreads();
        sm[t] += v;
        __syncthreads();
    }
    int p = sm[t] - s;
#pragma unroll
    for (int j = 0; j < 4; j++) {
        int n = base + j;
        if (n < NN) g_off[n] = p;
        p += c[j];
    }
    if (t == 255) g_btot[bx] = sm[255];
}

__global__ void k_scanB() {
    if (threadIdx.x == 0) {
        int s = 0;
        for (int i = 0; i < 49; i++) { g_boff[i] = s; s += g_btot[i]; }
    }
}

__global__ void k_scanC() {
    int i = blockIdx.x * blockDim.x + threadIdx.x;
    if (i >= NN) return;
    int v = g_off[i] + g_boff[i >> 10];
    g_off[i] = v;
    g_cur[i] = v;
}

__global__ void k_fill(const int* __restrict__ ei) {
    int i = blockIdx.x * blockDim.x + threadIdx.x;
    if (i >= 2 * EE) return;
    int r = (i >= EE) ? 1 : 0;
    int e = i - r * EE;
    int s = __ldg(ei + (size_t)r * 2 * EE + e);
    int d = __ldg(ei + (size_t)r * 2 * EE + EE + e);
    float nrm = g_isd[r * NN + s];
    int pos = atomicAdd(&g_cur[d], 1);
    g_ebuf[pos] = make_float2(__int_as_float(s | (r << 30)), nrm);
}

// fp16 conversions: features + transposed weights, one launch
__global__ void k_cvt(const float* __restrict__ x, const float* __restrict__ W) {
    int i = blockIdx.x * blockDim.x + threadIdx.x;
    if (i < NN * 32) {
        float4 v = ((const float4*)x)[i];
        __half2 a = __floats2half2_rn(v.x, v.y);
        __half2 b = __floats2half2_rn(v.z, v.w);
        ((uint2*)g_h16)[i] = make_uint2(*(unsigned*)&a, *(unsigned*)&b);
    } else if (i < NN * 32 + 2 * 128 * 256) {
        int j = i - NN * 32;
        int l = j >> 15, n = (j >> 8) & 127, k = j & 255;
        int r = k >> 7, kd = k & 127;
        g_w16[j] = __float2half(__ldg(W + (((size_t)(l * 2 + r) * 128 + kd) * 128 + n)));
    }
}

// ================= gather: h16 -> A fp16 [N][256] =================
__global__ __launch_bounds__(256) void k_gather() {
    int t = blockIdx.x * blockDim.x + threadIdx.x;
    int d = t >> 4;
    int l16 = t & 15;
    if (d >= NN) return;

    unsigned long long a0[4], a1[4];
    unsigned long long z = pack2(0.f, 0.f);
#pragma unroll
    for (int q = 0; q < 4; q++) { a0[q] = z; a1[q] = z; }

    const uint4* h = (const uint4*)g_h16;

    int e  = g_off[d];
    int e1 = (d < NN - 1) ? g_off[d + 1] : 2 * EE;

#define PROC(v, nrm, bits)                                                    \
    {                                                                         \
        const __half2* hp = (const __half2*)&(v);                             \
        float2 f0 = __half22float2(hp[0]);                                    \
        float2 f1 = __half22float2(hp[1]);                                    \
        float2 f2 = __half22float2(hp[2]);                                    \
        float2 f3 = __half22float2(hp[3]);                                    \
        float n0 = ((bits) & 0x40000000) ? 0.f : (nrm);                       \
        float n1 = (nrm) - n0;                                                \
        unsigned long long nn0 = pack2(n0, n0), nn1 = pack2(n1, n1);          \
        unsigned long long x0 = pack2(f0.x, f0.y), x1 = pack2(f1.x, f1.y);    \
        unsigned long long x2 = pack2(f2.x, f2.y), x3 = pack2(f3.x, f3.y);    \
        fma2(a0[0], x0, nn0); fma2(a0[1], x1, nn0);                           \
        fma2(a0[2], x2, nn0); fma2(a0[3], x3, nn0);                           \
        fma2(a1[0], x0, nn1); fma2(a1[1], x1, nn1);                           \
        fma2(a1[2], x2, nn1); fma2(a1[3], x3, nn1);                           \
    }

    for (; e + 1 < e1; e += 2) {
        float2 ea = g_ebuf[e];
        float2 eb = g_ebuf[e + 1];
        int ba = __float_as_int(ea.x);
        int bb = __float_as_int(eb.x);
        uint4 va = h[(size_t)(ba & 0x3FFFFFFF) * 16 + l16];
        uint4 vb = h[(size_t)(bb & 0x3FFFFFFF) * 16 + l16];
        PROC(va, ea.y, ba);
        PROC(vb, eb.y, bb);
    }
    if (e < e1) {
        float2 ea = g_ebuf[e];
        int ba = __float_as_int(ea.x);
        uint4 va = h[(size_t)(ba & 0x3FFFFFFF) * 16 + l16];
        PROC(va, ea.y, ba);
    }
#undef PROC

    // self-loop + isd[dst] scaling, convert to fp16
    uint4 sv = h[(size_t)d * 16 + l16];
    const __half2* sp = (const __half2*)&sv;
    float2 s0 = __half22float2(sp[0]);
    float2 s1 = __half22float2(sp[1]);
    float2 s2 = __half22float2(sp[2]);
    float2 s3 = __half22float2(sp[3]);
    float hs[8] = {s0.x, s0.y, s1.x, s1.y, s2.x, s2.y, s3.x, s3.y};
    float i0 = g_isd[d], i1 = g_isd[NN + d];

    union { uint4 q; __half2 h2[4]; } o0, o1;
#pragma unroll
    for (int q = 0; q < 4; q++) {
        float2 A0 = unpack2(a0[q]);
        float2 A1 = unpack2(a1[q]);
        float v0x = i0 * A0.x + i0 * i0 * hs[2 * q];
        float v0y = i0 * A0.y + i0 * i0 * hs[2 * q + 1];
        float v1x = i1 * A1.x + i1 * i1 * hs[2 * q];
        float v1y = i1 * A1.y + i1 * i1 * hs[2 * q + 1];
        o0.h2[q] = __floats2half2_rn(v0x, v0y);
        o1.h2[q] = __floats2half2_rn(v1x, v1y);
    }
    size_t base = (size_t)d * 256 + l16 * 8;
    *(uint4*)(g_a16 + base)       = o0.q;
    *(uint4*)(g_a16 + base + 128) = o1.q;
}

// ================= mma.sync fp16 GEMM: C[128-tile,128] = A[.,256] @ Wt^T + bias =================
// smem: buf0 @0 (16KB: A 8K + B 8K), buf1 @16384, bias @32768
#define MMA_SMEM (32768 + 512)

__device__ __forceinline__ void load_chunk(unsigned sbuf, int row0, int kc, int layer, int tid) {
    const __half* wt = g_w16 + (size_t)layer * 32768;
#pragma unroll
    for (int t = 0; t < 4; t++) {
        int cid = tid + t * 256;
        int reg = cid >> 9;             // 0 = A, 1 = B
        int idx = cid & 511;
        int row = idx >> 2;
        int ch  = idx & 3;
        unsigned dst = sbuf + reg * 8192 + row * 64 + ((ch ^ ((row >> 1) & 3)) << 4);
        if (reg == 0) {
            int grow = row0 + row;
            unsigned ok = (grow < NN) ? 16u : 0u;
            int gr = (grow < NN) ? grow : (NN - 1);
            cp16(dst, g_a16 + (size_t)gr * 256 + kc * 32 + ch * 8, ok);
        } else {
            cp16(dst, wt + (size_t)row * 256 + kc * 32 + ch * 8, 16u);
        }
    }
}

__global__ __launch_bounds__(256) void k_mma(const float* __restrict__ bias,
                                             const int* __restrict__ batch,
                                             int layer) {
    extern __shared__ char smem[];
    unsigned sb = smem_u32(smem);
    int tid  = threadIdx.x;
    int lane = tid & 31;
    int wid  = tid >> 5;
    int wm   = wid & 1;
    int wn   = wid >> 1;
    int row0 = blockIdx.x * 128;

    float* bias_s = (float*)(smem + 32768);
    if (tid < 128) bias_s[tid] = __ldg(bias + tid) + __ldg(bias + 128 + tid);

    float acc[4][4][4];
#pragma unroll
    for (int mt = 0; mt < 4; mt++)
#pragma unroll
        for (int nt = 0; nt < 4; nt++)
#pragma unroll
            for (int q = 0; q < 4; q++) acc[mt][nt][q] = 0.f;

    load_chunk(sb, row0, 0, layer, tid);
    cp_commit();

    for (int c = 0; c < 8; c++) {
        if (c + 1 < 8) {
            load_chunk(sb + ((c + 1) & 1) * 16384, row0, c + 1, layer, tid);
            cp_commit();
            cp_wait<1>();
        } else {
            cp_wait<0>();
        }
        __syncthreads();

        unsigned sbuf = sb + (c & 1) * 16384;
#pragma unroll
        for (int s = 0; s < 2; s++) {
            unsigned ah[4][4], bh[4][2];
#pragma unroll
            for (int mt = 0; mt < 4; mt++) {
                int rl = wm * 64 + mt * 16 + ((lane >> 3) & 1) * 8 + (lane & 7);
                int ch = 2 * s + (lane >> 4);
                unsigned ad = sbuf + rl * 64 + ((ch ^ ((rl >> 1) & 3)) << 4);
                ldm_x4(ah[mt][0], ah[mt][1], ah[mt][2], ah[mt][3], ad);
            }
#pragma unroll
            for (int p = 0; p < 2; p++) {
                int rl = wn * 32 + p * 16 + ((lane >> 4) & 1) * 8 + (lane & 7);
                int ch = 2 * s + ((lane >> 3) & 1);
                unsigned bd = sbuf + 8192 + rl * 64 + ((ch ^ ((rl >> 1) & 3)) << 4);
                unsigned r0, r1, r2, r3;
                ldm_x4(r0, r1, r2, r3, bd);
                bh[2 * p][0] = r0;     bh[2 * p][1] = r1;
                bh[2 * p + 1][0] = r2; bh[2 * p + 1][1] = r3;
            }
#pragma unroll
            for (int mt = 0; mt < 4; mt++)
#pragma unroll
                for (int nt = 0; nt < 4; nt++)
                    mma_f16(acc[mt][nt], ah[mt], bh[nt]);
        }
        __syncthreads();
    }

    // ---- epilogue ----
#pragma unroll
    for (int mt = 0; mt < 4; mt++) {
        int gm0 = row0 + wm * 64 + mt * 16 + (lane >> 2);
#pragma unroll
        for (int half = 0; half < 2; half++) {
            int gm = gm0 + half * 8;
            if (gm >= NN) continue;
            if (layer == 0) {
#pragma unroll
                for (int nt = 0; nt < 4; nt++) {
                    int cn = wn * 32 + nt * 8 + (lane & 3) * 2;
                    float v0 = fmaxf(acc[mt][nt][half * 2 + 0] + bias_s[cn], 0.f);
                    float v1 = fmaxf(acc[mt][nt][half * 2 + 1] + bias_s[cn + 1], 0.f);
                    *(__half2*)(g_h16 + (size_t)gm * 128 + cn) = __floats2half2_rn(v0, v1);
                }
            } else {
                int g = __ldg(batch + gm);
#pragma unroll
                for (int nt = 0; nt < 4; nt++) {
                    int cn = wn * 32 + nt * 8 + (lane & 3) * 2;
                    float v0 = acc[mt][nt][half * 2 + 0] + bias_s[cn];
                    float v1 = acc[mt][nt][half * 2 + 1] + bias_s[cn + 1];
                    float* p = g_pool + (size_t)g * 128 + cn;
                    asm volatile("red.global.add.v2.f32 [%0], {%1,%2};"
                                 :: "l"(p), "f"(v0), "f"(v1) : "memory");
                }
            }
        }
    }
}

// ================= final linear =================
__global__ void k_final(const float* __restrict__ lw, const float* __restrict__ lb,
                        float* __restrict__ out) {
    int tid = threadIdx.x;
    if (tid >= GGG * CCC) return;
    int g = tid >> 3, c = tid & 7;
    float cnt = fmaxf((float)g_bcnt[g], 1.0f);
    float s = 0.f;
#pragma unroll 8
    for (int k = 0; k < DDD; k++)
        s += g_pool[g * DDD + k] * __ldg(lw + k * CCC + c);
    out[tid] = s / cnt + __ldg(lb + c);
}

// ================= launch =================
extern "C" void kernel_launch(void* const* d_in, const int* in_sizes, int n_in,
                              void* d_out, int out_size) {
    const float* x     = (const float*)d_in[0];
    const float* W     = (const float*)d_in[1];
    const float* b     = (const float*)d_in[2];
    const float* lw    = (const float*)d_in[3];
    const float* lb    = (const float*)d_in[4];
    const int*   ei    = (const int*)d_in[5];
    const int*   batch = (const int*)d_in[6];
    float*       out   = (float*)d_out;

    cudaFuncSetAttribute(k_mma, cudaFuncAttributeMaxDynamicSharedMemorySize, MMA_SMEM);

    // prep
    k_zero<<<(2 * NN + 255) / 256, 256>>>();
    k_hist<<<(2 * EE + NN + 255) / 256, 256>>>(ei, batch);
    k_scanA<<<49, 256>>>();
    k_scanB<<<1, 32>>>();
    k_scanC<<<(NN + 255) / 256, 256>>>();
    k_fill<<<(2 * EE + 255) / 256, 256>>>(ei);
    k_cvt<<<(NN * 32 + 2 * 128 * 256 + 255) / 256, 256>>>(x, W);

    int mma_blocks = (NN + 127) / 128;
    int gat_blocks = (NN * 16 + 255) / 256;

    // layer 0
    k_gather<<<gat_blocks, 256>>>();
    k_mma<<<mma_blocks, 256, MMA_SMEM>>>(b, batch, 0);

    // layer 1
    k_gather<<<gat_blocks, 256>>>();
    k_mma<<<mma_blocks, 256, MMA_SMEM>>>(b + 2 * DDD, batch, 1);

    // classify
    k_final<<<1, 512>>>(lw, lb, out);
}